// round 3
// baseline (speedup 1.0000x reference)
#include <cuda_runtime.h>
#include <cuda_bf16.h>

// SwitchRouterLoss: out = 1e-3 * (z_loss + aux_loss)
//   z_loss   = mean over (g,t) of logsumexp(logits[g,t,:])^2
//   aux_loss = mean over (g,e) of (final_count[g,e]/T) * (prob_sum[g,e]/T) * E^2
// Capacity in token order collapses to closed form:
//   final_count[g,e>0] = min(c_e, cap)
//   final_count[g,0]   = min(c_0, cap) + sum_e max(c_e - cap, 0)   (drops -> expert 0)

constexpr int G = 64;
constexpr int T = 8192;
constexpr int E = 64;
constexpr int BPG = 2;                   // blocks per group
constexpr int NB = G * BPG;              // 128 blocks
constexpr int THREADS = 512;
constexpr int WARPS = THREADS / 32;      // 16
constexpr int TOK_PER_BLOCK = T / BPG;   // 4096
constexpr int ITERS = TOK_PER_BLOCK / (WARPS * 2);  // 128 (2 tokens per warp-iter)

__device__ int   d_Cp[NB * E];           // per-block argmax histograms
__device__ float d_Pp[NB * E];           // per-block prob sums
__device__ float d_Z[NB];                // per-block z partials
__device__ int   d_ticket = 0;           // last-block detector (reset each run)

__global__ __launch_bounds__(THREADS) void router_fused(const float* __restrict__ logits,
                                                        const int* __restrict__ cap_ptr,
                                                        float* __restrict__ out) {
    const int g    = blockIdx.x / BPG;
    const int blk  = blockIdx.x % BPG;
    const int warp = threadIdx.x >> 5;
    const int lane = threadIdx.x & 31;
    const int hl   = lane & 15;          // lane within half-warp
    const int half = lane >> 4;          // which token of the pair

    __shared__ int   sC[E];
    __shared__ float sP[E];
    __shared__ float sZ[WARPS * 2];

    if (threadIdx.x < E) { sC[threadIdx.x] = 0; sP[threadIdx.x] = 0.0f; }
    __syncthreads();

    const size_t tbase = (size_t)g * T + (size_t)blk * TOK_PER_BLOCK + (size_t)warp * (ITERS * 2);
    const float4* base = reinterpret_cast<const float4*>(logits + tbase * E);

    const int eidx = 4 * hl;             // this lane's experts within its token
    float p0 = 0.f, p1 = 0.f, p2 = 0.f, p3 = 0.f, zacc = 0.f;
    int   c0 = 0,   c1 = 0,   c2 = 0,   c3 = 0;

    #pragma unroll 4
    for (int i = 0; i < ITERS; i++) {
        float4 v = base[(size_t)(2 * i + half) * 16 + hl];

        // exp without max-shift (logits bounded): sum & max reduce in the same rounds
        float e0 = __expf(v.x), e1 = __expf(v.y), e2 = __expf(v.z), e3 = __expf(v.w);
        float s = (e0 + e1) + (e2 + e3);
        float m = fmaxf(fmaxf(v.x, v.y), fmaxf(v.z, v.w));

        #pragma unroll
        for (int o = 8; o; o >>= 1) {    // width-16 butterfly, stays in half-warp
            s += __shfl_xor_sync(0xFFFFFFFFu, s, o);
            m = fmaxf(m, __shfl_xor_sync(0xFFFFFFFFu, m, o));
        }

        // first-occurrence argmax (jnp tie rule)
        bool hit = (v.x == m) | (v.y == m) | (v.z == m) | (v.w == m);
        unsigned bal = __ballot_sync(0xFFFFFFFFu, hit);
        unsigned hb  = half ? (bal >> 16) : (bal & 0xFFFFu);
        int src = (__ffs(hb) - 1) + (half << 4);
        int my  = eidx + ((v.x == m) ? 0 : ((v.y == m) ? 1 : ((v.z == m) ? 2 : 3)));
        int e   = __shfl_sync(0xFFFFFFFFu, my, src);   // per-half-warp token's argmax

        float inv = __frcp_rn(s);
        p0 = fmaf(e0, inv, p0);
        p1 = fmaf(e1, inv, p1);
        p2 = fmaf(e2, inv, p2);
        p3 = fmaf(e3, inv, p3);

        // register histogram: owning lane counts (pure ALU, no atomics)
        int d = e - eidx;
        c0 += (d == 0); c1 += (d == 1); c2 += (d == 2); c3 += (d == 3);

        if (hl == 0) {
            float lz = __logf(s);
            zacc = fmaf(lz, lz, zacc);
        }
    }

    // combine warps in shared (one flush per lane)
    atomicAdd(&sP[eidx + 0], p0);
    atomicAdd(&sP[eidx + 1], p1);
    atomicAdd(&sP[eidx + 2], p2);
    atomicAdd(&sP[eidx + 3], p3);
    atomicAdd(&sC[eidx + 0], c0);
    atomicAdd(&sC[eidx + 1], c1);
    atomicAdd(&sC[eidx + 2], c2);
    atomicAdd(&sC[eidx + 3], c3);
    if (hl == 0) sZ[warp * 2 + half] = zacc;
    __syncthreads();

    if (threadIdx.x < E) {
        d_Cp[blockIdx.x * E + threadIdx.x] = sC[threadIdx.x];
        d_Pp[blockIdx.x * E + threadIdx.x] = sP[threadIdx.x];
    }
    if (threadIdx.x == 0) {
        float z = 0.f;
        #pragma unroll
        for (int w = 0; w < WARPS * 2; w++) z += sZ[w];
        d_Z[blockIdx.x] = z;
    }

    // ---- last-block fused finalize ----
    __shared__ bool isLast;
    __syncthreads();
    if (threadIdx.x == 0) {
        __threadfence();
        isLast = (atomicAdd(&d_ticket, 1) == NB - 1);
    }
    __syncthreads();
    if (!isLast) return;
    __threadfence();   // acquire: see all blocks' partials

    __shared__ int    fC[G * E];      // 16 KB
    __shared__ float  fP[G * E];      // 16 KB
    __shared__ double auxsh[G];
    __shared__ double zsh2[1];

    // sum per-group partials (BPG=2 each)
    for (int p = threadIdx.x; p < G * E; p += THREADS) {
        int gg = p / E, ee = p % E;
        int idx0 = (gg * BPG + 0) * E + ee;
        int idx1 = (gg * BPG + 1) * E + ee;
        fC[p] = d_Cp[idx0] + d_Cp[idx1];
        fP[p] = d_Pp[idx0] + d_Pp[idx1];
    }
    __syncthreads();

    if (threadIdx.x < G) {
        const int cap = *cap_ptr;
        const int gg = threadIdx.x;
        long dropped = 0;
        double aux = 0.0;
        #pragma unroll
        for (int ee = 0; ee < E; ee++) {
            int c = fC[gg * E + ee];
            int kept = (c < cap) ? c : cap;
            dropped += (c - kept);
            aux += (double)kept * (double)fP[gg * E + ee];
        }
        aux += (double)dropped * (double)fP[gg * E + 0];
        auxsh[gg] = aux;
    }
    if (threadIdx.x == 0) {
        double zs = 0.0;
        for (int b = 0; b < NB; b++) zs += (double)d_Z[b];
        zsh2[0] = zs;
        d_ticket = 0;                 // reset for next run / graph replay
    }
    __syncthreads();

    if (threadIdx.x == 0) {
        double aux = 0.0;
        #pragma unroll
        for (int gg = 0; gg < G; gg++) aux += auxsh[gg];
        const double dT = (double)T, dG = (double)G, dE = (double)E;
        double z_loss   = zsh2[0] / (dG * dT);
        double aux_loss = aux * dE / (dG * dT * dT);
        out[0] = (float)(0.001 * z_loss + 0.001 * aux_loss);
    }
}

extern "C" void kernel_launch(void* const* d_in, const int* in_sizes, int n_in,
                              void* d_out, int out_size) {
    const float* logits = (const float*)d_in[0];
    const int*   cap    = (const int*)d_in[2];
    float*       out    = (float*)d_out;

    router_fused<<<NB, THREADS>>>(logits, cap, out);
}

// round 4
// speedup vs baseline: 2.1283x; 2.1283x over previous
#include <cuda_runtime.h>
#include <cuda_bf16.h>

// SwitchRouterLoss: out = 1e-3 * (z_loss + aux_loss)
//   z_loss   = mean over (g,t) of logsumexp(logits[g,t,:])^2
//   aux_loss = mean over (g,e) of (final_count[g,e]/T) * (prob_sum[g,e]/T) * E^2
// Capacity in token order collapses to closed form:
//   final_count[g,e>0] = min(c_e, cap)
//   final_count[g,0]   = min(c_0, cap) + sum_e max(c_e - cap, 0)   (drops -> expert 0)

constexpr int G = 64;
constexpr int T = 8192;
constexpr int E = 64;
constexpr int BPG = 16;                  // blocks per group
constexpr int NB = G * BPG;              // 1024 blocks -> high occupancy
constexpr int THREADS = 256;
constexpr int WARPS = THREADS / 32;      // 8
constexpr int TOK_PER_BLOCK = T / BPG;   // 512
constexpr int ITERS = TOK_PER_BLOCK / (WARPS * 2);  // 32 (2 tokens per warp-iter)

// Global accumulators. Zero at module load; finalize re-zeroes after consuming
// so every graph replay starts clean.
__device__ int   d_C[G * E];
__device__ float d_P[G * E];
__device__ float d_Z[NB];
__device__ int   d_ticket = 0;

__global__ __launch_bounds__(THREADS) void router_fused(const float* __restrict__ logits,
                                                        const int* __restrict__ cap_ptr,
                                                        float* __restrict__ out) {
    const int g    = blockIdx.x / BPG;
    const int blk  = blockIdx.x % BPG;
    const int warp = threadIdx.x >> 5;
    const int lane = threadIdx.x & 31;
    const int hl   = lane & 15;          // lane within half-warp
    const int half = lane >> 4;          // which token of the pair

    __shared__ int   sC[E];
    __shared__ float sP[E];
    __shared__ float sZ[WARPS * 2];

    if (threadIdx.x < E) { sC[threadIdx.x] = 0; sP[threadIdx.x] = 0.0f; }
    __syncthreads();

    const size_t tbase = (size_t)g * T + (size_t)blk * TOK_PER_BLOCK + (size_t)warp * (ITERS * 2);
    const float4* base = reinterpret_cast<const float4*>(logits + tbase * E);

    const int eidx = 4 * hl;             // this lane's experts within its token
    float p0 = 0.f, p1 = 0.f, p2 = 0.f, p3 = 0.f, zacc = 0.f;
    int   c0 = 0,   c1 = 0,   c2 = 0,   c3 = 0;

    #pragma unroll 4
    for (int i = 0; i < ITERS; i++) {
        float4 v = base[(size_t)(2 * i + half) * 16 + hl];

        // exp without max-shift (logits bounded): sum & max reduce in the same rounds
        float e0 = __expf(v.x), e1 = __expf(v.y), e2 = __expf(v.z), e3 = __expf(v.w);
        float s = (e0 + e1) + (e2 + e3);
        float m = fmaxf(fmaxf(v.x, v.y), fmaxf(v.z, v.w));

        #pragma unroll
        for (int o = 8; o; o >>= 1) {    // width-16 butterfly, stays in half-warp
            s += __shfl_xor_sync(0xFFFFFFFFu, s, o);
            m = fmaxf(m, __shfl_xor_sync(0xFFFFFFFFu, m, o));
        }

        // first-occurrence argmax (jnp tie rule)
        bool hit = (v.x == m) | (v.y == m) | (v.z == m) | (v.w == m);
        unsigned bal = __ballot_sync(0xFFFFFFFFu, hit);
        unsigned hb  = half ? (bal >> 16) : (bal & 0xFFFFu);
        int src = (__ffs(hb) - 1) + (half << 4);
        int my  = eidx + ((v.x == m) ? 0 : ((v.y == m) ? 1 : ((v.z == m) ? 2 : 3)));
        int e   = __shfl_sync(0xFFFFFFFFu, my, src);

        float inv = __frcp_rn(s);
        p0 = fmaf(e0, inv, p0);
        p1 = fmaf(e1, inv, p1);
        p2 = fmaf(e2, inv, p2);
        p3 = fmaf(e3, inv, p3);

        // register histogram: owning lane counts (pure ALU, no atomics)
        int d = e - eidx;
        c0 += (d == 0); c1 += (d == 1); c2 += (d == 2); c3 += (d == 3);

        if (hl == 0) {
            float lz = __logf(s);
            zacc = fmaf(lz, lz, zacc);
        }
    }

    // combine warps in shared (one flush per lane)
    atomicAdd(&sP[eidx + 0], p0);
    atomicAdd(&sP[eidx + 1], p1);
    atomicAdd(&sP[eidx + 2], p2);
    atomicAdd(&sP[eidx + 3], p3);
    atomicAdd(&sC[eidx + 0], c0);
    atomicAdd(&sC[eidx + 1], c1);
    atomicAdd(&sC[eidx + 2], c2);
    atomicAdd(&sC[eidx + 3], c3);
    if (hl == 0) sZ[warp * 2 + half] = zacc;
    __syncthreads();

    // flush block totals straight into global accumulators (16 contenders/addr)
    if (threadIdx.x < E) {
        atomicAdd(&d_C[g * E + threadIdx.x], sC[threadIdx.x]);
        atomicAdd(&d_P[g * E + threadIdx.x], sP[threadIdx.x]);
    }
    if (threadIdx.x == 0) {
        float z = 0.f;
        #pragma unroll
        for (int w = 0; w < WARPS * 2; w++) z += sZ[w];
        d_Z[blockIdx.x] = z;
    }

    // ---- last-block fused finalize ----
    __shared__ bool isLast;
    __syncthreads();
    if (threadIdx.x == 0) {
        __threadfence();
        isLast = (atomicAdd(&d_ticket, 1) == NB - 1);
    }
    __syncthreads();
    if (!isLast) return;
    __threadfence();   // acquire: all blocks' flushes visible

    __shared__ double auxsh[G];
    __shared__ double zsh[WARPS];

    // z reduction: 1024 floats, 4 per thread
    {
        double zs = 0.0;
        for (int i = threadIdx.x; i < NB; i += THREADS) zs += (double)d_Z[i];
        #pragma unroll
        for (int o = 16; o; o >>= 1)
            zs += __shfl_xor_sync(0xFFFFFFFFu, __double2loint(0), 0) * 0.0 +
                  __shfl_down_sync(0xFFFFFFFFu, zs, o);
        if (lane == 0) zsh[warp] = zs;
    }

    // per-group capacity + aux (64 threads, one group each; 36KB of L2 reads)
    if (threadIdx.x < G) {
        const int cap = *cap_ptr;
        const int gg = threadIdx.x;
        long dropped = 0;
        double aux = 0.0;
        #pragma unroll
        for (int ee = 0; ee < E; ee++) {
            int c = d_C[gg * E + ee];
            int kept = (c < cap) ? c : cap;
            dropped += (c - kept);
            aux += (double)kept * (double)d_P[gg * E + ee];
        }
        aux += (double)dropped * (double)d_P[gg * E + 0];
        auxsh[gg] = aux;
    }
    __syncthreads();

    if (threadIdx.x == 0) {
        double aux = 0.0;
        #pragma unroll
        for (int gg = 0; gg < G; gg++) aux += auxsh[gg];
        double zs = 0.0;
        #pragma unroll
        for (int w = 0; w < WARPS; w++) zs += zsh[w];
        const double dT = (double)T, dG = (double)G, dE = (double)E;
        double z_loss   = zs / (dG * dT);
        double aux_loss = aux * dE / (dG * dT * dT);
        out[0] = (float)(0.001 * z_loss + 0.001 * aux_loss);
    }
    __syncthreads();

    // reset accumulators for the next run / graph replay
    for (int p = threadIdx.x; p < G * E; p += THREADS) { d_C[p] = 0; d_P[p] = 0.0f; }
    if (threadIdx.x == 0) d_ticket = 0;
}

extern "C" void kernel_launch(void* const* d_in, const int* in_sizes, int n_in,
                              void* d_out, int out_size) {
    const float* logits = (const float*)d_in[0];
    const int*   cap    = (const int*)d_in[2];
    float*       out    = (float*)d_out;

    router_fused<<<NB, THREADS>>>(logits, cap, out);
}